// round 2
// baseline (speedup 1.0000x reference)
#include <cuda_runtime.h>
#include <cstdint>
#include <cstddef>

// Problem constants
#define Bb 16
#define Tt 128
#define Dd 256
#define CLUSTER 8
#define NCOL 32              // Dd / CLUSTER columns per CTA
#define NTHREADS 512
#define NDPT 16              // d-elements per thread

__device__ __forceinline__ uint32_t my_cluster_rank() {
    uint32_t r;
    asm("mov.u32 %0, %%cluster_ctarank;" : "=r"(r));
    return r;
}

__device__ __forceinline__ void cluster_sync_() {
    asm volatile("barrier.cluster.arrive.aligned;" ::: "memory");
    asm volatile("barrier.cluster.wait.aligned;" ::: "memory");
}

__device__ __forceinline__ uint32_t mapa_u32(uint32_t laddr, uint32_t rank) {
    uint32_t r;
    asm("mapa.shared::cluster.u32 %0, %1, %2;" : "=r"(r) : "r"(laddr), "r"(rank));
    return r;
}

// Remote store that bumps the target CTA's mbarrier tx-count on completion.
__device__ __forceinline__ void st_async_f32(uint32_t raddr, float v, uint32_t rmbar) {
    asm volatile(
        "st.async.shared::cluster.mbarrier::complete_tx::bytes.b32 [%0], %1, [%2];"
        :: "r"(raddr), "r"(__float_as_uint(v)), "r"(rmbar) : "memory");
}

__device__ __forceinline__ void mb_init(uint32_t addr, uint32_t count) {
    asm volatile("mbarrier.init.shared.b64 [%0], %1;" :: "r"(addr), "r"(count) : "memory");
}

__device__ __forceinline__ void mb_expect(uint32_t addr, uint32_t bytes) {
    asm volatile("mbarrier.arrive.expect_tx.shared.b64 _, [%0], %1;"
                 :: "r"(addr), "r"(bytes) : "memory");
}

// Cluster-scope acquire wait (peer st.async data must be visible after this).
__device__ __forceinline__ void mb_wait(uint32_t addr, uint32_t parity) {
    uint32_t done;
    asm volatile(
        "{\n\t.reg .pred p;\n\t"
        "mbarrier.try_wait.parity.acquire.cluster.shared::cta.b64 p, [%1], %2;\n\t"
        "selp.b32 %0, 1, 0, p;\n\t}"
        : "=r"(done) : "r"(addr), "r"(parity) : "memory");
    while (!done) {
        asm volatile(
            "{\n\t.reg .pred p;\n\t"
            "mbarrier.try_wait.parity.acquire.cluster.shared::cta.b64 p, [%1], %2, 0x989680;\n\t"
            "selp.b32 %0, 1, 0, p;\n\t}"
            : "=r"(done) : "r"(addr), "r"(parity) : "memory");
    }
}

__device__ __forceinline__ float tanh_ap(float x) {
    float y;
    asm("tanh.approx.f32 %0, %1;" : "=f"(y) : "f"(x));
    return y;
}

__device__ __forceinline__ float grp16_sum(float v) {
    v += __shfl_xor_sync(0xffffffffu, v, 1);
    v += __shfl_xor_sync(0xffffffffu, v, 2);
    v += __shfl_xor_sync(0xffffffffu, v, 4);
    v += __shfl_xor_sync(0xffffffffu, v, 8);
    return v;
}

// Partial dot over this thread's 16 d-slots; saves yin for the deferred hebb update.
__device__ __forceinline__ float dot_part(const float* __restrict__ ys,
                                          const float (&h)[NDPT], const float (&w)[NDPT],
                                          const float (&a)[NDPT], int dbase,
                                          float (&yin)[NDPT]) {
    float s0 = 0.f, s1 = 0.f, s2 = 0.f, s3 = 0.f;
#pragma unroll
    for (int i = 0; i < NDPT; i += 4) {
        float4 v = *reinterpret_cast<const float4*>(ys + dbase + i);
        yin[i] = v.x; yin[i + 1] = v.y; yin[i + 2] = v.z; yin[i + 3] = v.w;
        s0 = fmaf(v.x, fmaf(a[i],     h[i],     w[i]),     s0);
        s1 = fmaf(v.y, fmaf(a[i + 1], h[i + 1], w[i + 1]), s1);
        s2 = fmaf(v.z, fmaf(a[i + 2], h[i + 2], w[i + 2]), s2);
        s3 = fmaf(v.w, fmaf(a[i + 3], h[i + 3], w[i + 3]), s3);
    }
    return (s0 + s1) + (s2 + s3);
}

__device__ __forceinline__ void hebb_upd(float (&h)[NDPT], const float (&yin)[NDPT],
                                         float yout, float eta, float om) {
    float ey = eta * yout;
#pragma unroll
    for (int i = 0; i < NDPT; i++) h[i] = fmaf(h[i], om, yin[i] * ey);
}

__global__ void __launch_bounds__(NTHREADS, 1) __cluster_dims__(CLUSTER, 1, 1)
plastic_kernel(const int* __restrict__ x, const float* __restrict__ emb,
               const float* __restrict__ ws, const float* __restrict__ alphas,
               const float* __restrict__ etas, float* __restrict__ out)
{
    // y version v lives in buf[v & 3]; 4-deep to tolerate 1-step CTA skew.
    __shared__ __align__(16) float y0b[4][Dd];
    __shared__ __align__(16) float y1b[4][Dd];
    __shared__ __align__(8) unsigned long long mbar[2];
    __shared__ float stage[Dd * NCOL];   // 32 KB startup staging
    __shared__ int   xtok[Tt];
    __shared__ float redbuf[2][8];

    const int tid     = threadIdx.x;
    const int batch   = blockIdx.x >> 3;
    const int rank    = (int)my_cluster_rank();
    const int e_local = tid >> 4;        // 0..31
    const int dgrp    = tid & 15;        // 0..15
    const int e0      = rank * NCOL;
    const int eg      = e0 + e_local;
    const int dbase   = dgrp * NDPT;

    const uint32_t mb0 = (uint32_t)__cvta_generic_to_shared(&mbar[0]);
    const uint32_t mb1 = (uint32_t)__cvta_generic_to_shared(&mbar[1]);

    if (tid == 0) {
        mb_init(mb0, 1);
        mb_init(mb1, 1);
        mb_expect(mb0, Dd * 4);          // iter 0: y0(0) only
        mb_expect(mb1, 2 * Dd * 4);      // iter 1: y1(0)+y0(1)
    }
    // zero y buffers
    for (int i = tid; i < 4 * Dd; i += NTHREADS) {
        y0b[i >> 8][i & 255] = 0.f;
        y1b[i >> 8][i & 255] = 0.f;
    }
    if (tid < Tt) xtok[tid] = x[batch * Tt + tid];
    __syncthreads();

    const float eta0 = etas[0], eta1 = etas[1];
    const float om0 = 1.0f - eta0, om1 = 1.0f - eta1;

    float h0[NDPT], h1[NDPT], w0[NDPT], w1[NDPT], a0[NDPT], a1[NDPT];
#pragma unroll
    for (int i = 0; i < NDPT; i++) { h0[i] = 0.f; h1[i] = 0.f; }

#define STAGE_LOAD(reg, gptr)                                             \
    __syncthreads();                                                      \
    for (int idx = tid; idx < Dd * NCOL; idx += NTHREADS) {               \
        int d = idx >> 5, j = idx & 31;                                   \
        stage[idx] = (gptr)[d * Dd + e0 + j];                             \
    }                                                                     \
    __syncthreads();                                                      \
    _Pragma("unroll")                                                     \
    for (int i = 0; i < NDPT; i++) reg[i] = stage[(dbase + i) * NCOL + e_local];

    STAGE_LOAD(w0, ws)
    STAGE_LOAD(w1, ws + Dd * Dd)
    STAGE_LOAD(a0, alphas)
    STAGE_LOAD(a1, alphas + Dd * Dd)
    __syncthreads();

    // per-thread peer address delta for rank = dgrp (only dgrp<8 threads store)
    const uint32_t smem0 = (uint32_t)__cvta_generic_to_shared(&y0b[0][0]);
    const uint32_t pd = (dgrp < CLUSTER) ? (mapa_u32(smem0, (uint32_t)dgrp) - smem0) : 0u;

    cluster_sync_();   // all mbarriers armed & buffers zeroed before any st.async

    // ---- prologue: y0(0) = tanh(emb[x0]) (hebb stays 0 since yin = 0) ----
    if (tid < Dd) {
        int e = tid >> 3;                 // 0..31 local column
        uint32_t rk = (uint32_t)(tid & 7);
        float v = tanh_ap(__ldg(&emb[(size_t)xtok[0] * Dd + e0 + e]));
        uint32_t la = (uint32_t)__cvta_generic_to_shared(&y0b[0][e0 + e]);
        uint32_t d2 = mapa_u32(smem0, rk) - smem0;
        st_async_f32(la + d2, v, mb0 + d2);
    }

    float* const outB = out + (size_t)batch * Tt * Dd;
    uint32_t par[2] = {0u, 0u};

    for (int t = 0; t <= Tt; ++t) {
        const int b = t & 1;
        mb_wait(b ? mb1 : mb0, par[b]);
        par[b] ^= 1u;
        if (tid == 0 && t + 2 <= Tt)   // re-arm this mbarrier for iter t+2
            mb_expect(b ? mb1 : mb0, (t + 2 == Tt) ? (Dd * 4) : (2 * Dd * 4));

        if (t < Tt) {
            // prefetch embedding input for layer0(t+1)
            float inp0 = 0.f;
            if (t + 1 < Tt) inp0 = __ldg(&emb[(size_t)xtok[t + 1] * Dd + eg]);
            const float inp1 = y0b[t & 3][eg];
            const uint32_t mb_next = ((t + 1) & 1) ? mb1 : mb0;

            // layer1(t): yin = y1(t-1)
            float yin1[NDPT];
            float acc1 = dot_part(y1b[(t + 3) & 3], h1, w1, a1, dbase, yin1);
            acc1 = grp16_sum(acc1);
            float y1v = tanh_ap(acc1 + inp1);
            if (dgrp < CLUSTER) {
                uint32_t la = (uint32_t)__cvta_generic_to_shared(&y1b[t & 3][eg]);
                st_async_f32(la + pd, y1v, mb_next + pd);
            }

            // layer0(t+1): yin = y0(t)
            if (t + 1 < Tt) {
                float yin0[NDPT];
                float acc0 = dot_part(y0b[t & 3], h0, w0, a0, dbase, yin0);
                acc0 = grp16_sum(acc0);
                float y0v = tanh_ap(acc0 + inp0);
                if (dgrp < CLUSTER) {
                    uint32_t la = (uint32_t)__cvta_generic_to_shared(&y0b[(t + 1) & 3][eg]);
                    st_async_f32(la + pd, y0v, mb_next + pd);
                }
                hebb_upd(h0, yin0, y0v, eta0, om0);
            }
            hebb_upd(h1, yin1, y1v, eta1, om1);
        }

        // ---- softmax(sigmoid(y1(t-1))) — overlaps with incoming traffic ----
        if (t >= 1) {
            const float* ys = y1b[(t + 3) & 3];
            float ex = 0.f;
            if (tid < Dd) {
                float yv = ys[tid];
                float s = 1.0f / (1.0f + __expf(-yv));
                ex = __expf(s);
            }
            float wsum = ex;
#pragma unroll
            for (int o = 16; o >= 1; o >>= 1) wsum += __shfl_xor_sync(0xffffffffu, wsum, o);
            const int wid = tid >> 5, lane = tid & 31;
            if (wid < 8 && lane == 0) redbuf[b][wid] = wsum;
            __syncthreads();
            float tot = 0.f;
#pragma unroll
            for (int k = 0; k < 8; k++) tot += redbuf[b][k];
            if (tid >= e0 && tid < e0 + NCOL)
                outB[(size_t)(t - 1) * Dd + tid] = __fdividef(ex, tot);
        }
    }

    cluster_sync_();   // don't exit with peer-targeted traffic conceptually open
}

extern "C" void kernel_launch(void* const* d_in, const int* in_sizes, int n_in,
                              void* d_out, int out_size) {
    const int*   x      = (const int*)d_in[0];
    const float* emb    = (const float*)d_in[1];
    const float* ws     = (const float*)d_in[2];
    const float* alphas = (const float*)d_in[3];
    const float* etas   = (const float*)d_in[4];
    plastic_kernel<<<Bb * CLUSTER, NTHREADS>>>(x, emb, ws, alphas, etas, (float*)d_out);
}

// round 3
// speedup vs baseline: 1.1334x; 1.1334x over previous
#include <cuda_runtime.h>
#include <cstdint>
#include <cstddef>

#define Bb 16
#define Tt 128
#define Dd 256
#define CLUSTER 8
#define NCOL 32              // columns per CTA
#define NTHREADS 512
#define NDPT 16              // d-elements per thread
#define NP 8                 // f32 pairs per thread

typedef unsigned long long u64;

__device__ __forceinline__ uint32_t my_cluster_rank() {
    uint32_t r; asm("mov.u32 %0, %%cluster_ctarank;" : "=r"(r)); return r;
}
__device__ __forceinline__ void cluster_sync_() {
    asm volatile("barrier.cluster.arrive.aligned;" ::: "memory");
    asm volatile("barrier.cluster.wait.aligned;" ::: "memory");
}
__device__ __forceinline__ void cluster_arrive_() {
    asm volatile("barrier.cluster.arrive.aligned;" ::: "memory");
}
__device__ __forceinline__ void cluster_wait_() {
    asm volatile("barrier.cluster.wait.aligned;" ::: "memory");
}
__device__ __forceinline__ uint32_t mapa_u32(uint32_t laddr, uint32_t rank) {
    uint32_t r;
    asm("mapa.shared::cluster.u32 %0, %1, %2;" : "=r"(r) : "r"(laddr), "r"(rank));
    return r;
}
__device__ __forceinline__ void st_remote(uint32_t addr, float v) {
    asm volatile("st.shared::cluster.f32 [%0], %1;" :: "r"(addr), "f"(v) : "memory");
}
__device__ __forceinline__ float tanh_ap(float x) {
    float y; asm("tanh.approx.f32 %0, %1;" : "=f"(y) : "f"(x)); return y;
}
__device__ __forceinline__ u64 fma2(u64 a, u64 b, u64 c) {
    u64 d; asm("fma.rn.f32x2 %0, %1, %2, %3;" : "=l"(d) : "l"(a), "l"(b), "l"(c)); return d;
}
__device__ __forceinline__ u64 mul2(u64 a, u64 b) {
    u64 d; asm("mul.rn.f32x2 %0, %1, %2;" : "=l"(d) : "l"(a), "l"(b)); return d;
}
__device__ __forceinline__ u64 pack2(float x, float y) {
    u64 d;
    asm("mov.b64 %0, {%1, %2};" : "=l"(d)
        : "r"(__float_as_uint(x)), "r"(__float_as_uint(y)));
    return d;
}
__device__ __forceinline__ float2 unpack2(u64 v) {
    uint32_t lo, hi;
    asm("mov.b64 {%0, %1}, %2;" : "=r"(lo), "=r"(hi) : "l"(v));
    return make_float2(__uint_as_float(lo), __uint_as_float(hi));
}
__device__ __forceinline__ float grp16_sum(float v) {
    v += __shfl_xor_sync(0xffffffffu, v, 1);
    v += __shfl_xor_sync(0xffffffffu, v, 2);
    v += __shfl_xor_sync(0xffffffffu, v, 4);
    v += __shfl_xor_sync(0xffffffffu, v, 8);
    return v;
}

// Packed partial dot: sum_i yin[i] * (a[i]*h[i] + w[i]) over this thread's 16 d's.
__device__ __forceinline__ float dot2(const float* __restrict__ ys, int dbase,
                                      const u64 (&h)[NP], const u64 (&w)[NP],
                                      const u64 (&a)[NP]) {
    const ulonglong2* yp = reinterpret_cast<const ulonglong2*>(ys + dbase);
    u64 s0 = 0ull, s1 = 0ull;
#pragma unroll
    for (int i = 0; i < NP; i += 2) {
        ulonglong2 yv = yp[i >> 1];
        s0 = fma2(yv.x, fma2(a[i],     h[i],     w[i]),     s0);
        s1 = fma2(yv.y, fma2(a[i + 1], h[i + 1], w[i + 1]), s1);
    }
    float2 f0 = unpack2(s0), f1 = unpack2(s1);
    return (f0.x + f0.y) + (f1.x + f1.y);
}

// Deferred hebb update: h = om*h + (eta*yout)*yin, yin re-read from smem.
__device__ __forceinline__ void hebb2(u64 (&h)[NP], const float* __restrict__ ys,
                                      int dbase, float ey, u64 om2) {
    const ulonglong2* yp = reinterpret_cast<const ulonglong2*>(ys + dbase);
    u64 ey2 = pack2(ey, ey);
#pragma unroll
    for (int i = 0; i < NP; i += 2) {
        ulonglong2 yv = yp[i >> 1];
        h[i]     = fma2(h[i],     om2, mul2(yv.x, ey2));
        h[i + 1] = fma2(h[i + 1], om2, mul2(yv.y, ey2));
    }
}

__global__ void __launch_bounds__(NTHREADS, 1) __cluster_dims__(CLUSTER, 1, 1)
plastic_kernel(const int* __restrict__ x, const float* __restrict__ emb,
               const float* __restrict__ ws, const float* __restrict__ alphas,
               const float* __restrict__ etas, float* __restrict__ out)
{
    __shared__ __align__(16) float y0b[4][Dd];   // y0 version v in [v & 3]
    __shared__ __align__(16) float y1b[4][Dd];
    __shared__ float stage[Dd * NCOL];           // startup staging (32 KB)
    __shared__ int   xtok[Tt];
    __shared__ float redbuf[2][8];

    const int tid     = threadIdx.x;
    const int batch   = blockIdx.x >> 3;
    const int rank    = (int)my_cluster_rank();
    const int e_local = tid >> 4;
    const int dgrp    = tid & 15;
    const int e0      = rank * NCOL;
    const int eg      = e0 + e_local;
    const int dbase   = dgrp * NDPT;
    const int wid     = tid >> 5, lane = tid & 31;

    // init
    for (int i = tid; i < 4 * Dd; i += NTHREADS) {
        y0b[i >> 8][i & 255] = 0.f;
        y1b[i >> 8][i & 255] = 0.f;
    }
    if (tid < Tt) xtok[tid] = x[batch * Tt + tid];
    __syncthreads();

    const float eta0 = etas[0], eta1 = etas[1];
    const u64 om0_2 = pack2(1.f - eta0, 1.f - eta0);
    const u64 om1_2 = pack2(1.f - eta1, 1.f - eta1);

    u64 h0[NP], h1[NP], w0[NP], w1[NP], a0[NP], a1[NP];
#pragma unroll
    for (int i = 0; i < NP; i++) { h0[i] = 0ull; h1[i] = 0ull; }

#define STAGE_LOAD(reg, gptr)                                              \
    __syncthreads();                                                       \
    for (int idx = tid; idx < Dd * NCOL; idx += NTHREADS) {                \
        int d = idx >> 5, j = idx & 31;                                    \
        stage[idx] = (gptr)[d * Dd + e0 + j];                              \
    }                                                                      \
    __syncthreads();                                                       \
    _Pragma("unroll")                                                      \
    for (int i = 0; i < NP; i++)                                           \
        reg[i] = pack2(stage[(dbase + 2 * i) * NCOL + e_local],            \
                       stage[(dbase + 2 * i + 1) * NCOL + e_local]);

    STAGE_LOAD(w0, ws)
    STAGE_LOAD(w1, ws + Dd * Dd)
    STAGE_LOAD(a0, alphas)
    STAGE_LOAD(a1, alphas + Dd * Dd)
    __syncthreads();

    // prologue: every CTA computes the FULL y0(0) = tanh(emb[x0]) locally
    for (int i = tid; i < Dd; i += NTHREADS)
        y0b[0][i] = tanh_ap(__ldg(&emb[(size_t)xtok[0] * Dd + i]));
    __syncthreads();

    // peer address delta for rank = dgrp (only dgrp<8 threads remote-store)
    const uint32_t smem0 = (uint32_t)__cvta_generic_to_shared(&y0b[0][0]);
    const uint32_t pd = (dgrp < CLUSTER) ? (mapa_u32(smem0, (uint32_t)dgrp) - smem0) : 0u;

    cluster_sync_();   // everyone's buffers zeroed before any remote store

    float* const outB = out + (size_t)batch * Tt * Dd;
    float embreg = __ldg(&emb[(size_t)xtok[1] * Dd + eg]);

    for (int t = 0; t < Tt; ++t) {
        const int c3 = t & 3, p3 = (t + 3) & 3, n3 = (t + 1) & 3;

        // ---- critical path: recurrence only ----
        float acc1 = dot2(y1b[p3], dbase, h1, w1, a1);
        acc1 = grp16_sum(acc1);
        float y1v = tanh_ap(acc1 + y0b[c3][eg]);
        if (dgrp < CLUSTER)
            st_remote((uint32_t)__cvta_generic_to_shared(&y1b[c3][eg]) + pd, y1v);

        float y0v = 0.f;
        if (t + 1 < Tt) {
            float acc0 = dot2(y0b[c3], dbase, h0, w0, a0);
            acc0 = grp16_sum(acc0);
            y0v = tanh_ap(acc0 + embreg);
            if (dgrp < CLUSTER)
                st_remote((uint32_t)__cvta_generic_to_shared(&y0b[n3][eg]) + pd, y0v);
        }

        cluster_arrive_();   // release: peers can proceed as soon as stores drain

        // ---- deferred work, overlapped with peer skew + barrier latency ----
        hebb2(h1, y1b[p3], dbase, eta1 * y1v, om1_2);
        if (t + 1 < Tt) hebb2(h0, y0b[c3], dbase, eta0 * y0v, om0_2);
        if (t + 2 < Tt) embreg = __ldg(&emb[(size_t)xtok[t + 2] * Dd + eg]);

        if (t >= 1) {   // out(t-1) = softmax(sigmoid(y1(t-1))), y1(t-1) in buf p3
            float ex = 0.f;
            if (tid < Dd) {
                float yv = y1b[p3][tid];
                float s = __fdividef(1.0f, 1.0f + __expf(-yv));
                ex = __expf(s);
            }
            float wsum = ex;
#pragma unroll
            for (int o = 16; o >= 1; o >>= 1)
                wsum += __shfl_xor_sync(0xffffffffu, wsum, o);
            if (wid < 8 && lane == 0) redbuf[t & 1][wid] = wsum;
            __syncthreads();
            float tot = 0.f;
#pragma unroll
            for (int k = 0; k < 8; k++) tot += redbuf[t & 1][k];
            if (tid >= e0 && tid < e0 + NCOL)
                outB[(size_t)(t - 1) * Dd + tid] = __fdividef(ex, tot);
        }

        cluster_wait_();
    }

    // epilogue: out(Tt-1) from y1(Tt-1) = buf (Tt-1)&3
    {
        const float* ys = y1b[(Tt - 1) & 3];
        float ex = 0.f;
        if (tid < Dd) {
            float yv = ys[tid];
            float s = __fdividef(1.0f, 1.0f + __expf(-yv));
            ex = __expf(s);
        }
        float wsum = ex;
#pragma unroll
        for (int o = 16; o >= 1; o >>= 1)
            wsum += __shfl_xor_sync(0xffffffffu, wsum, o);
        if (wid < 8 && lane == 0) redbuf[0][wid] = wsum;
        __syncthreads();
        float tot = 0.f;
#pragma unroll
        for (int k = 0; k < 8; k++) tot += redbuf[0][k];
        if (tid >= e0 && tid < e0 + NCOL)
            outB[(size_t)(Tt - 1) * Dd + tid] = __fdividef(ex, tot);
    }

    cluster_sync_();
}

extern "C" void kernel_launch(void* const* d_in, const int* in_sizes, int n_in,
                              void* d_out, int out_size) {
    const int*   x      = (const int*)d_in[0];
    const float* emb    = (const float*)d_in[1];
    const float* ws     = (const float*)d_in[2];
    const float* alphas = (const float*)d_in[3];
    const float* etas   = (const float*)d_in[4];
    plastic_kernel<<<Bb * CLUSTER, NTHREADS>>>(x, emb, ws, alphas, etas, (float*)d_out);
}

// round 4
// speedup vs baseline: 1.2045x; 1.0627x over previous
#include <cuda_runtime.h>
#include <cstdint>
#include <cstddef>

#define Bb 16
#define Tt 128
#define Dd 256
#define CLUSTER 8
#define NCOL 32              // columns per CTA
#define NTHREADS 512
#define NDPT 16              // d-elements per thread

__device__ __forceinline__ uint32_t my_cluster_rank() {
    uint32_t r; asm("mov.u32 %0, %%cluster_ctarank;" : "=r"(r)); return r;
}
__device__ __forceinline__ void cluster_sync_() {
    asm volatile("barrier.cluster.arrive.aligned;" ::: "memory");
    asm volatile("barrier.cluster.wait.aligned;" ::: "memory");
}
__device__ __forceinline__ uint32_t mapa_u32(uint32_t laddr, uint32_t rank) {
    uint32_t r;
    asm("mapa.shared::cluster.u32 %0, %1, %2;" : "=r"(r) : "r"(laddr), "r"(rank));
    return r;
}
__device__ __forceinline__ void st_remote(uint32_t addr, float v) {
    asm volatile("st.shared::cluster.f32 [%0], %1;" :: "r"(addr), "f"(v) : "memory");
}
// Release store of the step flag into a peer CTA's smem.
__device__ __forceinline__ void st_flag_release(uint32_t addr, int v) {
    asm volatile("st.release.cluster.shared::cluster.u32 [%0], %1;"
                 :: "r"(addr), "r"(v) : "memory");
}
// Acquire poll of a local smem flag.
__device__ __forceinline__ int ld_flag_acquire(uint32_t addr) {
    int v;
    asm volatile("ld.acquire.cluster.shared::cta.u32 %0, [%1];"
                 : "=r"(v) : "r"(addr) : "memory");
    return v;
}
__device__ __forceinline__ float tanh_ap(float x) {
    float y; asm("tanh.approx.f32 %0, %1;" : "=f"(y) : "f"(x)); return y;
}
__device__ __forceinline__ float grp16_sum(float v) {
    v += __shfl_xor_sync(0xffffffffu, v, 1);
    v += __shfl_xor_sync(0xffffffffu, v, 2);
    v += __shfl_xor_sync(0xffffffffu, v, 4);
    v += __shfl_xor_sync(0xffffffffu, v, 8);
    return v;
}

// Partial dot: sum_i yin[i] * (a[i]*h[i] + w[i]) over this thread's 16 d's.
__device__ __forceinline__ float dot_part(const float* __restrict__ ys, int dbase,
                                          const float (&h)[NDPT], const float (&w)[NDPT],
                                          const float (&a)[NDPT]) {
    float s0 = 0.f, s1 = 0.f, s2 = 0.f, s3 = 0.f;
#pragma unroll
    for (int i = 0; i < NDPT; i += 4) {
        float4 v = *reinterpret_cast<const float4*>(ys + dbase + i);
        s0 = fmaf(v.x, fmaf(a[i],     h[i],     w[i]),     s0);
        s1 = fmaf(v.y, fmaf(a[i + 1], h[i + 1], w[i + 1]), s1);
        s2 = fmaf(v.z, fmaf(a[i + 2], h[i + 2], w[i + 2]), s2);
        s3 = fmaf(v.w, fmaf(a[i + 3], h[i + 3], w[i + 3]), s3);
    }
    return (s0 + s1) + (s2 + s3);
}

// Deferred hebb update: h = om*h + (eta*yout)*yin, yin re-read from smem.
__device__ __forceinline__ void hebb_upd(float (&h)[NDPT], const float* __restrict__ ys,
                                         int dbase, float ey, float om) {
#pragma unroll
    for (int i = 0; i < NDPT; i += 4) {
        float4 v = *reinterpret_cast<const float4*>(ys + dbase + i);
        h[i]     = fmaf(h[i],     om, v.x * ey);
        h[i + 1] = fmaf(h[i + 1], om, v.y * ey);
        h[i + 2] = fmaf(h[i + 2], om, v.z * ey);
        h[i + 3] = fmaf(h[i + 3], om, v.w * ey);
    }
}

__global__ void __launch_bounds__(NTHREADS, 1) __cluster_dims__(CLUSTER, 1, 1)
plastic_kernel(const int* __restrict__ x, const float* __restrict__ emb,
               const float* __restrict__ ws, const float* __restrict__ alphas,
               const float* __restrict__ etas, float* __restrict__ out)
{
    __shared__ __align__(16) float y0b[4][Dd];   // y0 version v in [v & 3]
    __shared__ __align__(16) float y1b[4][Dd];
    __shared__ float stage[Dd * NCOL];           // startup staging (32 KB)
    __shared__ int   xtok[Tt];
    __shared__ float redbuf[8];
    __shared__ int   flags[CLUSTER];             // flags[r] = last step completed by rank r

    const int tid     = threadIdx.x;
    const int batch   = blockIdx.x >> 3;
    const int rank    = (int)my_cluster_rank();
    const int e_local = tid >> 4;
    const int dgrp    = tid & 15;
    const int e0      = rank * NCOL;
    const int eg      = e0 + e_local;
    const int dbase   = dgrp * NDPT;
    const int wid     = tid >> 5, lane = tid & 31;

    // init shared state
    for (int i = tid; i < 4 * Dd; i += NTHREADS) {
        y0b[i >> 8][i & 255] = 0.f;
        y1b[i >> 8][i & 255] = 0.f;
    }
    if (tid < Tt) xtok[tid] = x[batch * Tt + tid];
    if (tid < CLUSTER) flags[tid] = 0;
    __syncthreads();

    const float eta0 = etas[0], eta1 = etas[1];
    const float om0 = 1.f - eta0, om1 = 1.f - eta1;

    float h0[NDPT], h1[NDPT], w0[NDPT], w1[NDPT], a0[NDPT], a1[NDPT];
#pragma unroll
    for (int i = 0; i < NDPT; i++) { h0[i] = 0.f; h1[i] = 0.f; }

#define STAGE_LOAD(reg, gptr)                                              \
    __syncthreads();                                                       \
    for (int idx = tid; idx < Dd * NCOL; idx += NTHREADS) {                \
        int d = idx >> 5, j = idx & 31;                                    \
        stage[idx] = (gptr)[d * Dd + e0 + j];                              \
    }                                                                      \
    __syncthreads();                                                       \
    _Pragma("unroll")                                                      \
    for (int i = 0; i < NDPT; i++) reg[i] = stage[(dbase + i) * NCOL + e_local];

    STAGE_LOAD(w0, ws)
    STAGE_LOAD(w1, ws + Dd * Dd)
    STAGE_LOAD(a0, alphas)
    STAGE_LOAD(a1, alphas + Dd * Dd)
    __syncthreads();

    // prologue: every CTA computes the FULL y0(0) = tanh(emb[x0]) locally (no comms)
    for (int i = tid; i < Dd; i += NTHREADS)
        y0b[0][i] = tanh_ap(__ldg(&emb[(size_t)xtok[0] * Dd + i]));
    __syncthreads();

    // peer deltas
    const uint32_t smem0 = (uint32_t)__cvta_generic_to_shared(&y0b[0][0]);
    const uint32_t pd = (dgrp < CLUSTER) ? (mapa_u32(smem0, (uint32_t)dgrp) - smem0) : 0u;
    // flag publish address: write flags[rank] in peer CTA (tid) 's smem
    const uint32_t myflag_l = (uint32_t)__cvta_generic_to_shared(&flags[rank]);
    const uint32_t flag_raddr = (tid < CLUSTER) ? mapa_u32(myflag_l, (uint32_t)tid) : 0u;
    const uint32_t pollflag = (uint32_t)__cvta_generic_to_shared(&flags[0]) + 4u * (uint32_t)tid;

    cluster_sync_();   // everyone's buffers zeroed + flags armed before any remote store

    float* const outB = out + (size_t)batch * Tt * Dd;
    float embreg = __ldg(&emb[(size_t)xtok[1] * Dd + eg]);

    for (int t = 0; t < Tt; ++t) {
        const int c3 = t & 3, p3 = (t + 3) & 3, n3 = (t + 1) & 3;

        // ---- critical path: recurrence only ----
        float acc1 = dot_part(y1b[p3], dbase, h1, w1, a1);
        float acc0 = (t + 1 < Tt) ? dot_part(y0b[c3], dbase, h0, w0, a0) : 0.f;
        acc1 = grp16_sum(acc1);
        float y1v = tanh_ap(acc1 + y0b[c3][eg]);
        if (dgrp < CLUSTER)
            st_remote((uint32_t)__cvta_generic_to_shared(&y1b[c3][eg]) + pd, y1v);

        float y0v = 0.f;
        if (t + 1 < Tt) {
            acc0 = grp16_sum(acc0);
            y0v = tanh_ap(acc0 + embreg);
            if (dgrp < CLUSTER)
                st_remote((uint32_t)__cvta_generic_to_shared(&y0b[n3][eg]) + pd, y0v);
        }

        __syncthreads();                         // all y stores issued before flag release
        if (tid < CLUSTER) st_flag_release(flag_raddr, t + 1);

        // ---- deferred work, overlapped with flag propagation ----
        hebb_upd(h1, y1b[p3], dbase, eta1 * y1v, om1);
        if (t + 1 < Tt) hebb_upd(h0, y0b[c3], dbase, eta0 * y0v, om0);
        if (t + 2 < Tt) embreg = __ldg(&emb[(size_t)xtok[t + 2] * Dd + eg]);

        if (t >= 1) {   // out(t-1) = softmax(sigmoid(y1(t-1))) ; y1(t-1) in buf p3
            float ex = 0.f;
            if (tid < Dd) {
                float yv = y1b[p3][tid];
                float s = __fdividef(1.0f, 1.0f + __expf(-yv));
                ex = __expf(s);
            }
            float wsum = ex;
#pragma unroll
            for (int o = 16; o >= 1; o >>= 1)
                wsum += __shfl_xor_sync(0xffffffffu, wsum, o);
            if (wid < 8 && lane == 0) redbuf[wid] = wsum;
            __syncthreads();
            float tot = 0.f;
#pragma unroll
            for (int k = 0; k < 8; k++) tot += redbuf[k];
            if (tid >= e0 && tid < e0 + NCOL)
                outB[(size_t)(t - 1) * Dd + tid] = __fdividef(ex, tot);
        }

        // ---- wait for all 8 ranks to finish step t ----
        if (tid < CLUSTER) {
            while (ld_flag_acquire(pollflag) < t + 1) { }
        }
        __syncthreads();
    }

    // epilogue: out(Tt-1) from y1(Tt-1) in buf (Tt-1)&3
    {
        const float* ys = y1b[(Tt - 1) & 3];
        float ex = 0.f;
        if (tid < Dd) {
            float yv = ys[tid];
            float s = __fdividef(1.0f, 1.0f + __expf(-yv));
            ex = __expf(s);
        }
        float wsum = ex;
#pragma unroll
        for (int o = 16; o >= 1; o >>= 1)
            wsum += __shfl_xor_sync(0xffffffffu, wsum, o);
        if (wid < 8 && lane == 0) redbuf[wid] = wsum;
        __syncthreads();
        float tot = 0.f;
#pragma unroll
        for (int k = 0; k < 8; k++) tot += redbuf[k];
        if (tid >= e0 && tid < e0 + NCOL)
            outB[(size_t)(Tt - 1) * Dd + tid] = __fdividef(ex, tot);
    }

    cluster_sync_();   // keep smem alive until all peers finished reading
}

extern "C" void kernel_launch(void* const* d_in, const int* in_sizes, int n_in,
                              void* d_out, int out_size) {
    const int*   x      = (const int*)d_in[0];
    const float* emb    = (const float*)d_in[1];
    const float* ws     = (const float*)d_in[2];
    const float* alphas = (const float*)d_in[3];
    const float* etas   = (const float*)d_in[4];
    plastic_kernel<<<Bb * CLUSTER, NTHREADS>>>(x, emb, ws, alphas, etas, (float*)d_out);
}

// round 5
// speedup vs baseline: 1.4965x; 1.2424x over previous
#include <cuda_runtime.h>
#include <cuda_fp16.h>
#include <cstdint>
#include <cstddef>

#define Bb 16
#define Tt 128
#define Dd 256
#define CLUSTER 4
#define HCOLS 128            // columns per CTA (one layer, half the columns)
#define NTHREADS 512
#define NDPT 64              // d-elements per thread
#define NPAIR 32             // half2 pairs per thread

__device__ __forceinline__ uint32_t my_cluster_rank() {
    uint32_t r; asm("mov.u32 %0, %%cluster_ctarank;" : "=r"(r)); return r;
}
__device__ __forceinline__ void cluster_sync_() {
    asm volatile("barrier.cluster.arrive.aligned;" ::: "memory");
    asm volatile("barrier.cluster.wait.aligned;" ::: "memory");
}
__device__ __forceinline__ uint32_t mapa_u32(uint32_t laddr, uint32_t rank) {
    uint32_t r;
    asm("mapa.shared::cluster.u32 %0, %1, %2;" : "=r"(r) : "r"(laddr), "r"(rank));
    return r;
}
__device__ __forceinline__ void st_remote(uint32_t addr, float v) {
    asm volatile("st.shared::cluster.f32 [%0], %1;" :: "r"(addr), "f"(v) : "memory");
}
__device__ __forceinline__ void st_flag_release(uint32_t addr, int v) {
    asm volatile("st.release.cluster.shared::cluster.u32 [%0], %1;"
                 :: "r"(addr), "r"(v) : "memory");
}
__device__ __forceinline__ int ld_flag_acquire(uint32_t addr) {
    int v;
    asm volatile("ld.acquire.cluster.shared::cta.u32 %0, [%1];"
                 : "=r"(v) : "r"(addr) : "memory");
    return v;
}
__device__ __forceinline__ void poll_ge(uint32_t addr, int target) {
    while (ld_flag_acquire(addr) < target) { }
}
__device__ __forceinline__ float tanh_ap(float x) {
    float y; asm("tanh.approx.f32 %0, %1;" : "=f"(y) : "f"(x)); return y;
}
__device__ __forceinline__ float grp4_sum(float v) {
    v += __shfl_xor_sync(0xffffffffu, v, 1);
    v += __shfl_xor_sync(0xffffffffu, v, 2);
    return v;
}

__global__ void __launch_bounds__(NTHREADS, 1) __cluster_dims__(CLUSTER, 1, 1)
plastic_kernel(const int* __restrict__ x, const float* __restrict__ emb,
               const float* __restrict__ ws, const float* __restrict__ alphas,
               const float* __restrict__ etas, float* __restrict__ out)
{
    // ybuf[s] holds this CTA's LAYER y-vector for step s (mod 4), full 256
    __shared__ __align__(16) float ybuf[4][Dd];
    __shared__ __align__(16) float y0h[4][HCOLS];   // L1 only: incoming y0 own-half
    __shared__ __align__(16) float stage[64 * HCOLS]; // 32 KB staging
    __shared__ int   xtok[Tt];
    __shared__ int   flags[4];     // [0]=partner_y, [1]=y0_ready (L1), [2]=credit (L0)
    __shared__ float redbuf[8];

    const int tid     = threadIdx.x;
    const int batch   = blockIdx.x >> 2;
    const int rank    = (int)my_cluster_rank();
    const int layer   = rank >> 1;          // 0: L0 CTAs, 1: L1 CTAs
    const int half    = rank & 1;
    const int col_off = half * HCOLS;
    const int partner = rank ^ 1;
    const int col     = tid >> 2;           // 0..127
    const int colg    = col_off + col;
    const int dgrp    = tid & 3;            // 0..3
    const int dbase   = dgrp * NDPT;
    const int wid     = tid >> 5, lane = tid & 31;

    // init shared
    for (int i = tid; i < 4 * Dd; i += NTHREADS) ybuf[i >> 8][i & 255] = 0.f;
    for (int i = tid; i < 4 * HCOLS; i += NTHREADS) y0h[i >> 7][i & 127] = 0.f;
    if (tid < 4) flags[tid] = 0;
    if (tid < Tt) xtok[tid] = x[batch * Tt + tid];
    __syncthreads();

    const float eta = etas[layer];
    const float om  = 1.0f - eta;
    const __half2 om2 = __float2half2_rn(om);

    // ---- load my layer's w/alpha slice into fp16 registers (staged, coalesced) ----
    __half2 w2[NPAIR], a2[NPAIR], h2[NPAIR];
#pragma unroll
    for (int i = 0; i < NPAIR; i++) h2[i] = __float2half2_rn(0.f);

    const float* wsrc = ws     + (size_t)layer * Dd * Dd;
    const float* asrc = alphas + (size_t)layer * Dd * Dd;
#define STAGE_H2(dst, gptr)                                                  \
    for (int c = 0; c < 4; ++c) {                                            \
        __syncthreads();                                                     \
        for (int k = 0; k < 16; ++k) {                                       \
            int idx = tid + k * NTHREADS;                                    \
            int dd = idx >> 7, j = idx & 127;                                \
            stage[idx] = (gptr)[(size_t)(c * 64 + dd) * Dd + col_off + j];   \
        }                                                                    \
        __syncthreads();                                                     \
        if (dgrp == c) {                                                     \
            _Pragma("unroll")                                                \
            for (int p = 0; p < NPAIR; ++p)                                  \
                dst[p] = __floats2half2_rn(stage[(2 * p) * HCOLS + col],     \
                                           stage[(2 * p + 1) * HCOLS + col]);\
        }                                                                    \
    }
    STAGE_H2(w2, wsrc)
    STAGE_H2(a2, asrc)
    __syncthreads();

    // ---- peer addresses ----
    const uint32_t yb0   = (uint32_t)__cvta_generic_to_shared(&ybuf[0][0]);
    const uint32_t pdel  = mapa_u32(yb0, (uint32_t)partner) - yb0;   // partner ybuf delta
    const uint32_t y0b0  = (uint32_t)__cvta_generic_to_shared(&y0h[0][0]);
    const uint32_t y0del = (layer == 0) ? (mapa_u32(y0b0, (uint32_t)(rank + 2)) - y0b0) : 0u;
    const uint32_t fb    = (uint32_t)__cvta_generic_to_shared(&flags[0]);
    const uint32_t f_partner = mapa_u32(fb + 0u, (uint32_t)partner);
    const uint32_t f_y0      = (layer == 0) ? mapa_u32(fb + 4u, (uint32_t)(rank + 2)) : 0u;
    const uint32_t f_credit  = (layer == 1) ? mapa_u32(fb + 8u, (uint32_t)(rank - 2)) : 0u;
    const uint32_t pf_partner = fb + 0u;
    const uint32_t pf_y0      = fb + 4u;
    const uint32_t pf_credit  = fb + 8u;

    cluster_sync_();   // buffers zeroed, flags armed, weights loaded everywhere

    float* const outB = out + (size_t)batch * Tt * Dd;
    float embreg = (layer == 0) ? __ldg(&emb[(size_t)xtok[0] * Dd + colg]) : 0.f;

    for (int t = 0; t < Tt; ++t) {
        // ---- waits ----
        poll_ge(pf_partner, t);                       // partner finished step t-1
        if (layer == 1) poll_ge(pf_y0, t + 1);        // y0(t) delivered
        else if (t >= 4) poll_ge(pf_credit, t - 3);   // ring credit

        const int sp = (t + 3) & 3;                   // slot of y(t-1)
        const int sc = t & 3;                         // slot of y(t)

        // ---- dot: sum_d yin[d] * (a*h + w)[d, colg] ----
        const float* yin = ybuf[sp] + dbase;
        float s0 = 0.f, s1 = 0.f, s2 = 0.f, s3 = 0.f;
#pragma unroll
        for (int i = 0; i < NPAIR; i += 2) {
            float4 yv = *reinterpret_cast<const float4*>(yin + 2 * i);
            float2 t0 = __half22float2(__hfma2(a2[i],     h2[i],     w2[i]));
            float2 t1 = __half22float2(__hfma2(a2[i + 1], h2[i + 1], w2[i + 1]));
            s0 = fmaf(yv.x, t0.x, s0);
            s1 = fmaf(yv.y, t0.y, s1);
            s2 = fmaf(yv.z, t1.x, s2);
            s3 = fmaf(yv.w, t1.y, s3);
        }
        float acc = grp4_sum((s0 + s1) + (s2 + s3));
        const float inp = (layer == 0) ? embreg : y0h[sc][col];
        const float y = tanh_ap(acc + inp);

        // ---- push y(t): own-half locally + to partner; L0 also to its L1 ----
        const uint32_t la = (uint32_t)__cvta_generic_to_shared(&ybuf[sc][colg]);
        if (dgrp == 1) ybuf[sc][colg] = y;
        if (dgrp == 0) st_remote(la + pdel, y);
        if (dgrp == 2 && layer == 0) {
            const uint32_t l0a = (uint32_t)__cvta_generic_to_shared(&y0h[sc][col]);
            st_remote(l0a + y0del, y);
        }
        __syncthreads();
        if (tid == 0) st_flag_release(f_partner, t + 1);
        if (tid == 32 && layer == 0) st_flag_release(f_y0, t + 1);
        if (tid == 32 && layer == 1) st_flag_release(f_credit, t + 1);

        // ---- deferred (overlaps flag/data flight) ----
        {   // hebb: h = om*h + (eta*y) * yin
            const float ey = eta * y;
#pragma unroll
            for (int i = 0; i < NPAIR; i += 2) {
                float4 yv = *reinterpret_cast<const float4*>(yin + 2 * i);
                h2[i]     = __hfma2(h2[i],     om2, __floats2half2_rn(yv.x * ey, yv.y * ey));
                h2[i + 1] = __hfma2(h2[i + 1], om2, __floats2half2_rn(yv.z * ey, yv.w * ey));
            }
        }
        if (layer == 0) {
            if (t + 1 < Tt) embreg = __ldg(&emb[(size_t)xtok[t + 1] * Dd + colg]);
        } else if (t >= 1) {
            // out(t-1) = softmax(sigmoid(y1(t-1))); y1(t-1) full in ybuf[sp]
            float ex = 0.f;
            if (tid < Dd) {
                float yv = ybuf[sp][tid];
                float s = __fdividef(1.0f, 1.0f + __expf(-yv));
                ex = __expf(s);
            }
            float wsum = ex;
#pragma unroll
            for (int o = 16; o >= 1; o >>= 1)
                wsum += __shfl_xor_sync(0xffffffffu, wsum, o);
            if (wid < 8 && lane == 0) redbuf[wid] = wsum;
            __syncthreads();
            float tot = 0.f;
#pragma unroll
            for (int k = 0; k < 8; k++) tot += redbuf[k];
            if (tid >= col_off && tid < col_off + HCOLS)
                outB[(size_t)(t - 1) * Dd + tid] = __fdividef(ex, tot);
        }
    }

    // ---- epilogue: L1 writes out(Tt-1) once partner's final half arrives ----
    if (layer == 1) {
        poll_ge(pf_partner, Tt);
        const float* ys = ybuf[(Tt - 1) & 3];
        float ex = 0.f;
        if (tid < Dd) {
            float yv = ys[tid];
            float s = __fdividef(1.0f, 1.0f + __expf(-yv));
            ex = __expf(s);
        }
        float wsum = ex;
#pragma unroll
        for (int o = 16; o >= 1; o >>= 1)
            wsum += __shfl_xor_sync(0xffffffffu, wsum, o);
        if (wid < 8 && lane == 0) redbuf[wid] = wsum;
        __syncthreads();
        float tot = 0.f;
#pragma unroll
        for (int k = 0; k < 8; k++) tot += redbuf[k];
        if (tid >= col_off && tid < col_off + HCOLS)
            outB[(size_t)(Tt - 1) * Dd + tid] = __fdividef(ex, tot);
    }

    cluster_sync_();   // keep smem alive until all peers are done
}

extern "C" void kernel_launch(void* const* d_in, const int* in_sizes, int n_in,
                              void* d_out, int out_size) {
    const int*   x      = (const int*)d_in[0];
    const float* emb    = (const float*)d_in[1];
    const float* ws     = (const float*)d_in[2];
    const float* alphas = (const float*)d_in[3];
    const float* etas   = (const float*)d_in[4];
    plastic_kernel<<<Bb * CLUSTER, NTHREADS>>>(x, emb, ws, alphas, etas, (float*)d_out);
}